// round 1
// baseline (speedup 1.0000x reference)
#include <cuda_runtime.h>
#include <math.h>

// Problem constants (Gemma2 attention layer)
#define T_SEQ 2048
#define HID   3584
#define NH    16
#define NKV   8
#define HD    256
#define QKV_COLS ((NH + 2 * NKV) * HD)   // 8192
#define Q_OFF 0
#define K_OFF (NH * HD)                  // 4096
#define V_OFF ((NH + NKV) * HD)          // 6144
#define ATTN_COLS (NH * HD)              // 4096

#define SOFT_CAP 50.0f
#define ATTN_SCALE 0.0625f               // 256^-0.5

// ---------------------------------------------------------------------------
// Scratch (static __device__ globals; allocation inside kernel_launch is banned)
// ---------------------------------------------------------------------------
__device__ float g_qkv[(size_t)T_SEQ * QKV_COLS];            // 64 MB
__device__ float g_scores[(size_t)NH * T_SEQ * T_SEQ];       // 256 MB
__device__ float g_attn[(size_t)T_SEQ * ATTN_COLS];          // 32 MB

// ---------------------------------------------------------------------------
// Generic 128x128x8 register-blocked SGEMM.
//   C[z] = A[z] * B[z / bDiv]      (TB=false: B is [K,N] row-major)
//                                  (TB=true : B is [N,K] row-major -> C = A B^T)
// EPI==1: scores epilogue: softcap(tanh) + causal mask (col > row -> -inf)
// All dims must be divisible: M%128==0, N%128==0, K%8==0 (true for every call).
// ---------------------------------------------------------------------------
template<bool TB, int EPI>
__global__ __launch_bounds__(256)
void sgemm128(const float* __restrict__ A, const float* __restrict__ B,
              float* __restrict__ C,
              int M, int N, int K, int lda, int ldb, int ldc,
              long long sA, long long sB, long long sC, int bDiv)
{
    constexpr int BM = 128, BN = 128, BK = 8, TM = 8, TN = 8;
    __shared__ float As[BK][BM];
    __shared__ float Bs[BK][BN];

    const int z = blockIdx.z;
    A += (long long)z * sA;
    B += (long long)(z / bDiv) * sB;
    C += (long long)z * sC;

    const int tid  = threadIdx.x;
    const int row0 = blockIdx.y * BM;
    const int col0 = blockIdx.x * BN;

    const int tRow = (tid / 16) * TM;
    const int tCol = (tid % 16) * TN;

    // A (and NT-B) loader: 1 float4 per thread along K, scattered transposed
    const int aRow = tid >> 1;           // 0..127
    const int aCol = (tid & 1) * 4;      // 0 or 4
    // NN-B loader: 1 float4 per thread along N
    const int bRow = tid >> 5;           // 0..7
    const int bCol = (tid & 31) * 4;     // 0..124

    const float* Aptr    = A + (long long)(row0 + aRow) * lda + aCol;
    const float* BptrNT  = B + (long long)(col0 + aRow) * ldb + aCol;
    const float* BptrNN  = B + (long long)bRow * ldb + col0 + bCol;

    float acc[TM][TN] = {};

    for (int k0 = 0; k0 < K; k0 += BK) {
        float4 av = *reinterpret_cast<const float4*>(Aptr + k0);
        As[aCol + 0][aRow] = av.x;
        As[aCol + 1][aRow] = av.y;
        As[aCol + 2][aRow] = av.z;
        As[aCol + 3][aRow] = av.w;
        if (TB) {
            float4 bv = *reinterpret_cast<const float4*>(BptrNT + k0);
            Bs[aCol + 0][aRow] = bv.x;
            Bs[aCol + 1][aRow] = bv.y;
            Bs[aCol + 2][aRow] = bv.z;
            Bs[aCol + 3][aRow] = bv.w;
        } else {
            float4 bv = *reinterpret_cast<const float4*>(BptrNN + (long long)k0 * ldb);
            *reinterpret_cast<float4*>(&Bs[bRow][bCol]) = bv;
        }
        __syncthreads();

        #pragma unroll
        for (int kk = 0; kk < BK; kk++) {
            float ra[TM], rb[TN];
            #pragma unroll
            for (int m = 0; m < TM; m++) ra[m] = As[kk][tRow + m];
            #pragma unroll
            for (int n = 0; n < TN; n++) rb[n] = Bs[kk][tCol + n];
            #pragma unroll
            for (int m = 0; m < TM; m++)
                #pragma unroll
                for (int n = 0; n < TN; n++)
                    acc[m][n] = fmaf(ra[m], rb[n], acc[m][n]);
        }
        __syncthreads();
    }

    #pragma unroll
    for (int m = 0; m < TM; m++) {
        const int r = row0 + tRow + m;
        #pragma unroll
        for (int n = 0; n < TN; n++) {
            const int c = col0 + tCol + n;
            float v = acc[m][n];
            if (EPI == 1) {
                v = SOFT_CAP * tanhf(v * (ATTN_SCALE / SOFT_CAP));
                if (c > r) v = -INFINITY;
            }
            C[(long long)r * ldc + c] = v;
        }
    }
}

// ---------------------------------------------------------------------------
// Neox-style RoPE over the full head dim, in place on Q and K inside g_qkv.
// heads 0..15 -> Q head h ; heads 16..23 -> K head h-16.
// ---------------------------------------------------------------------------
__global__ __launch_bounds__(256)
void rope_kernel(float* __restrict__ qkv, const int* __restrict__ positions)
{
    int idx = blockIdx.x * blockDim.x + threadIdx.x;          // T*24*128 threads
    int i = idx & 127;
    int h = (idx >> 7) % (NH + NKV);
    int t = idx / (128 * (NH + NKV));
    if (t >= T_SEQ) return;

    float pos = (float)positions[t];
    // inv_freq = theta^(-(2i)/d)
    float inv = powf(10000.0f, -((2.0f * (float)i) / (float)HD));
    float f = pos * inv;
    float c = cosf(f), s = sinf(f);

    int col = (h < NH) ? (h * HD) : (K_OFF + (h - NH) * HD);
    float* p = qkv + (long long)t * QKV_COLS + col;
    float x1 = p[i];
    float x2 = p[i + HD / 2];
    p[i]          = x1 * c - x2 * s;
    p[i + HD / 2] = x2 * c + x1 * s;
}

// ---------------------------------------------------------------------------
// Row softmax over scores[h][q][:]  (masked entries are -inf -> exp = 0)
// grid = (T_SEQ, NH), 256 threads
// ---------------------------------------------------------------------------
__global__ __launch_bounds__(256)
void softmax_kernel(float* __restrict__ s)
{
    float* row = s + ((long long)blockIdx.y * T_SEQ + blockIdx.x) * (long long)T_SEQ;
    const int tid = threadIdx.x, lane = tid & 31, wid = tid >> 5;
    __shared__ float redm[8];
    __shared__ float reds[8];

    float m = -INFINITY;
    for (int i = tid; i < T_SEQ; i += 256) m = fmaxf(m, row[i]);
    #pragma unroll
    for (int o = 16; o; o >>= 1) m = fmaxf(m, __shfl_xor_sync(0xffffffffu, m, o));
    if (lane == 0) redm[wid] = m;
    __syncthreads();
    if (tid < 8) {
        float v = redm[tid];
        #pragma unroll
        for (int o = 4; o; o >>= 1) v = fmaxf(v, __shfl_xor_sync(0xffu, v, o));
        if (tid == 0) redm[0] = v;
    }
    __syncthreads();
    m = redm[0];

    float sum = 0.0f;
    for (int i = tid; i < T_SEQ; i += 256) {
        float e = expf(row[i] - m);
        row[i] = e;
        sum += e;
    }
    #pragma unroll
    for (int o = 16; o; o >>= 1) sum += __shfl_xor_sync(0xffffffffu, sum, o);
    if (lane == 0) reds[wid] = sum;
    __syncthreads();
    if (tid < 8) {
        float v = reds[tid];
        #pragma unroll
        for (int o = 4; o; o >>= 1) v += __shfl_xor_sync(0xffu, v, o);
        if (tid == 0) reds[0] = v;
    }
    __syncthreads();
    float inv = 1.0f / reds[0];
    for (int i = tid; i < T_SEQ; i += 256) row[i] *= inv;
}

// ---------------------------------------------------------------------------
// kernel_launch — graph-capturable, allocation-free
// ---------------------------------------------------------------------------
extern "C" void kernel_launch(void* const* d_in, const int* in_sizes, int n_in,
                              void* d_out, int out_size)
{
    const int*   positions = (const int*)  d_in[0];
    const float* hidden    = (const float*)d_in[1];
    const float* w_qkv     = (const float*)d_in[2];
    const float* w_o       = (const float*)d_in[3];
    float*       out       = (float*)d_out;

    float *qkv, *scores, *attn;
    cudaGetSymbolAddress((void**)&qkv,    g_qkv);
    cudaGetSymbolAddress((void**)&scores, g_scores);
    cudaGetSymbolAddress((void**)&attn,   g_attn);

    // 1) QKV projection: [T, HID] @ [HID, 8192]
    sgemm128<false, 0><<<dim3(QKV_COLS / 128, T_SEQ / 128, 1), 256>>>(
        hidden, w_qkv, qkv,
        T_SEQ, QKV_COLS, HID, HID, QKV_COLS, QKV_COLS,
        0, 0, 0, 1);

    // 2) RoPE on Q and K (in place)
    rope_kernel<<<(T_SEQ * (NH + NKV) * (HD / 2)) / 256, 256>>>(qkv, positions);

    // 3) scores[h] = softcap(Q_h K_{h/2}^T * scale) with causal mask   (NT, batched)
    sgemm128<true, 1><<<dim3(T_SEQ / 128, T_SEQ / 128, NH), 256>>>(
        qkv + Q_OFF, qkv + K_OFF, scores,
        T_SEQ, T_SEQ, HD, QKV_COLS, QKV_COLS, T_SEQ,
        (long long)HD, (long long)HD, (long long)T_SEQ * T_SEQ, 2);

    // 4) row softmax
    softmax_kernel<<<dim3(T_SEQ, NH), 256>>>(scores);

    // 5) attn[h] = P_h @ V_{h/2}   (NN, batched) -> g_attn[t, h*HD + d]
    sgemm128<false, 0><<<dim3(HD / 128, T_SEQ / 128, NH), 256>>>(
        scores, qkv + V_OFF, attn,
        T_SEQ, HD, T_SEQ, T_SEQ, QKV_COLS, ATTN_COLS,
        (long long)T_SEQ * T_SEQ, (long long)HD, (long long)HD, 2);

    // 6) output projection: [T, 4096] @ [4096, HID]
    sgemm128<false, 0><<<dim3(HID / 128, T_SEQ / 128, 1), 256>>>(
        attn, w_o, out,
        T_SEQ, HID, ATTN_COLS, ATTN_COLS, HID, HID,
        0, 0, 0, 1);
}

// round 3
// speedup vs baseline: 4.0947x; 4.0947x over previous
#include <cuda_runtime.h>
#include <cuda_bf16.h>
#include <math.h>
#include <stdint.h>

// ---------------------------------------------------------------------------
// Problem constants
// ---------------------------------------------------------------------------
#define T_SEQ 2048
#define HID   3584
#define NH    16
#define NKV   8
#define HD    256
#define QKV_COLS ((NH + 2 * NKV) * HD)   // 8192
#define K_OFF (NH * HD)                  // 4096
#define V_OFF ((NH + NKV) * HD)          // 6144
#define ATTN_COLS (NH * HD)              // 4096

#define SOFT_CAP 50.0f
#define ATTN_SCALE 0.0625f               // 256^-0.5
#define NEG_INF __int_as_float(0xff800000)

// ---------------------------------------------------------------------------
// Static device scratch
// ---------------------------------------------------------------------------
__device__ float g_qkv[(size_t)T_SEQ * QKV_COLS];              // fp32 qkv
__device__ float g_scores[(size_t)NH * T_SEQ * T_SEQ];         // fp32 scores

__device__ __nv_bfloat16 g_hc_h[(size_t)T_SEQ * HID];
__device__ __nv_bfloat16 g_hc_l[(size_t)T_SEQ * HID];
__device__ __nv_bfloat16 g_wqkvT_h[(size_t)QKV_COLS * HID];
__device__ __nv_bfloat16 g_wqkvT_l[(size_t)QKV_COLS * HID];
__device__ __nv_bfloat16 g_woT_h[(size_t)HID * ATTN_COLS];
__device__ __nv_bfloat16 g_woT_l[(size_t)HID * ATTN_COLS];
__device__ __nv_bfloat16 g_qkvc_h[(size_t)T_SEQ * QKV_COLS];
__device__ __nv_bfloat16 g_qkvc_l[(size_t)T_SEQ * QKV_COLS];
__device__ __nv_bfloat16 g_vTc_h[(size_t)NKV * HD * T_SEQ];
__device__ __nv_bfloat16 g_vTc_l[(size_t)NKV * HD * T_SEQ];
__device__ __nv_bfloat16 g_p_h[(size_t)NH * T_SEQ * T_SEQ];
__device__ __nv_bfloat16 g_p_l[(size_t)NH * T_SEQ * T_SEQ];
__device__ __nv_bfloat16 g_attnc_h[(size_t)T_SEQ * ATTN_COLS];
__device__ __nv_bfloat16 g_attnc_l[(size_t)T_SEQ * ATTN_COLS];

// ---------------------------------------------------------------------------
// PTX helpers (sm_80-level: cp.async + ldmatrix + mma.sync)
// ---------------------------------------------------------------------------
__device__ __forceinline__ uint32_t smem_u32(const void* p) {
    uint32_t a;
    asm("{ .reg .u64 t; cvta.to.shared.u64 t, %1; cvt.u32.u64 %0, t; }" : "=r"(a) : "l"(p));
    return a;
}
__device__ __forceinline__ void ldgsts16(uint32_t s, const void* g) {
    asm volatile("cp.async.cg.shared.global [%0], [%1], 16;" :: "r"(s), "l"(g));
}
__device__ __forceinline__ void ldsm4(uint32_t* r, uint32_t a) {
    asm volatile("ldmatrix.sync.aligned.m8n8.x4.shared.b16 {%0,%1,%2,%3}, [%4];"
        : "=r"(r[0]), "=r"(r[1]), "=r"(r[2]), "=r"(r[3]) : "r"(a));
}
__device__ __forceinline__ void mma16816(float* d, const uint32_t* a, const uint32_t* b) {
    asm volatile("mma.sync.aligned.m16n8k16.row.col.f32.bf16.bf16.f32 "
        "{%0,%1,%2,%3}, {%4,%5,%6,%7}, {%8,%9}, {%0,%1,%2,%3};"
        : "+f"(d[0]), "+f"(d[1]), "+f"(d[2]), "+f"(d[3])
        : "r"(a[0]), "r"(a[1]), "r"(a[2]), "r"(a[3]), "r"(b[0]), "r"(b[1]));
}

// ---------------------------------------------------------------------------
// HMMA GEMM:  C[z] = A[z] @ B[z/bDiv]^T
//   A: [M,K] row-major (hi/lo bf16), B: [N,K] row-major (hi/lo bf16)
//   3-pass split accumulation: AhBh + AhBl + AlBh (fp32 accum)
//   Tile: BM=128, BN=128, BK=64, 256 threads (warps 2x4, warp tile 64x32)
// EPI: 0 = fp32 store; 1 = scores softcap (no mask; upper tiles skipped);
//      2 = split-bf16 pair store (Ch, Cl)
// CAUSAL: 1 = skip tiles fully above diagonal; 2 = truncate K at diagonal
// ---------------------------------------------------------------------------
#define STAGE_B 65536                    // Ah 16K | Al 16K | Bh 16K | Bl 16K
#define GEMM_SMEM (2 * STAGE_B + 1024)

template<int EPI, int CAUSAL>
__global__ void __launch_bounds__(256, 1)
gemm_mma(const __nv_bfloat16* __restrict__ Ah, const __nv_bfloat16* __restrict__ Al,
         const __nv_bfloat16* __restrict__ Bh, const __nv_bfloat16* __restrict__ Bl,
         float* __restrict__ C, __nv_bfloat16* __restrict__ Ch, __nv_bfloat16* __restrict__ Cl,
         int K, int lda, int ldb, int ldc,
         long long sA, long long sB, long long sC, int bDiv)
{
    extern __shared__ char dsm[];
    const int tid = threadIdx.x;
    const int wid = tid >> 5;
    const int lane = tid & 31;
    const int row0 = blockIdx.y * 128;
    const int col0 = blockIdx.x * 128;

    if (CAUSAL == 1 && col0 >= row0 + 128) return;   // fully masked: never read

    const long long z = blockIdx.z;
    Ah += z * sA;  Al += z * sA;
    Bh += (z / bDiv) * sB;  Bl += (z / bDiv) * sB;

    const uint32_t raw = smem_u32(dsm);
    const uint32_t sb0 = (raw + 1023) & ~1023u;

    int nCh = K >> 6;
    if (CAUSAL == 2) { int lim = (row0 >> 6) + 2; if (lim < nCh) nCh = lim; }

    float acc[4][4][4];
    #pragma unroll
    for (int a = 0; a < 4; a++)
        #pragma unroll
        for (int b = 0; b < 4; b++)
            #pragma unroll
            for (int c = 0; c < 4; c++) acc[a][b][c] = 0.0f;

    const int m0w = (wid & 1) * 64;
    const int n0w = (wid >> 1) * 32;
    const int aRowL = lane & 15;
    const int aColL = (lane >> 4) << 3;
    const int bRowL = (lane & 7) + ((lane >> 4) << 3);
    const int bColL = ((lane >> 3) & 1) << 3;

    // ---- stage loader: 4 arrays x 128 rows x 64 bf16 (128B rows, SW128 swizzle)
    auto issue = [&](int ic) {
        const int k0 = ic << 6;
        const uint32_t st = sb0 + (ic & 1) * STAGE_B;
        #pragma unroll
        for (int i = 0; i < 4; i++) {
            int t = tid + i * 256;
            int r = t >> 3, chn = t & 7;
            uint32_t off = (uint32_t)(r * 128 + chn * 16);
            off ^= (off >> 3) & 0x70;
            long long ga = (long long)(row0 + r) * lda + k0 + chn * 8;
            long long gb = (long long)(col0 + r) * ldb + k0 + chn * 8;
            ldgsts16(st + off,         Ah + ga);
            ldgsts16(st + 16384 + off, Al + ga);
            ldgsts16(st + 32768 + off, Bh + gb);
            ldgsts16(st + 49152 + off, Bl + gb);
        }
    };

    issue(0);
    asm volatile("cp.async.commit_group;" ::: "memory");

    for (int ic = 0; ic < nCh; ic++) {
        if (ic + 1 < nCh) issue(ic + 1);
        asm volatile("cp.async.commit_group;" ::: "memory");
        asm volatile("cp.async.wait_group 1;" ::: "memory");
        __syncthreads();

        const uint32_t st = sb0 + (ic & 1) * STAGE_B;
        #pragma unroll
        for (int ks = 0; ks < 4; ks++) {
            const int k0e = ks * 16;
            uint32_t ah[4][4], al[4][4], bh[2][4], bl[2][4];
            #pragma unroll
            for (int mt = 0; mt < 4; mt++) {
                uint32_t off = (uint32_t)((m0w + mt * 16 + aRowL) * 128 + (k0e + aColL) * 2);
                off ^= (off >> 3) & 0x70;
                ldsm4(ah[mt], st + off);
            }
            #pragma unroll
            for (int p = 0; p < 2; p++) {
                uint32_t off = (uint32_t)((n0w + p * 16 + bRowL) * 128 + (k0e + bColL) * 2);
                off ^= (off >> 3) & 0x70;
                ldsm4(bh[p], st + 32768 + off);
            }
            #pragma unroll
            for (int mt = 0; mt < 4; mt++)
                #pragma unroll
                for (int nt = 0; nt < 4; nt++)
                    mma16816(acc[mt][nt], ah[mt], &bh[nt >> 1][(nt & 1) * 2]);
            #pragma unroll
            for (int p = 0; p < 2; p++) {
                uint32_t off = (uint32_t)((n0w + p * 16 + bRowL) * 128 + (k0e + bColL) * 2);
                off ^= (off >> 3) & 0x70;
                ldsm4(bl[p], st + 49152 + off);
            }
            #pragma unroll
            for (int mt = 0; mt < 4; mt++)
                #pragma unroll
                for (int nt = 0; nt < 4; nt++)
                    mma16816(acc[mt][nt], ah[mt], &bl[nt >> 1][(nt & 1) * 2]);
            #pragma unroll
            for (int mt = 0; mt < 4; mt++) {
                uint32_t off = (uint32_t)((m0w + mt * 16 + aRowL) * 128 + (k0e + aColL) * 2);
                off ^= (off >> 3) & 0x70;
                ldsm4(al[mt], st + 16384 + off);
            }
            #pragma unroll
            for (int mt = 0; mt < 4; mt++)
                #pragma unroll
                for (int nt = 0; nt < 4; nt++)
                    mma16816(acc[mt][nt], al[mt], &bh[nt >> 1][(nt & 1) * 2]);
        }
        __syncthreads();
    }

    // ---- register epilogue
    if (EPI <= 1) C += z * sC;
    else { Ch += z * sC; Cl += z * sC; }

    #pragma unroll
    for (int mt = 0; mt < 4; mt++) {
        #pragma unroll
        for (int nt = 0; nt < 4; nt++) {
            const int r = row0 + m0w + mt * 16 + (lane >> 2);
            const int c = col0 + n0w + nt * 8 + (lane & 3) * 2;
            float d0 = acc[mt][nt][0], d1 = acc[mt][nt][1];
            float d2 = acc[mt][nt][2], d3 = acc[mt][nt][3];
            if (EPI == 1) {
                d0 = SOFT_CAP * tanhf(d0 * (ATTN_SCALE / SOFT_CAP));
                d1 = SOFT_CAP * tanhf(d1 * (ATTN_SCALE / SOFT_CAP));
                d2 = SOFT_CAP * tanhf(d2 * (ATTN_SCALE / SOFT_CAP));
                d3 = SOFT_CAP * tanhf(d3 * (ATTN_SCALE / SOFT_CAP));
            }
            if (EPI <= 1) {
                *reinterpret_cast<float2*>(C + (long long)r * ldc + c)       = make_float2(d0, d1);
                *reinterpret_cast<float2*>(C + (long long)(r + 8) * ldc + c) = make_float2(d2, d3);
            } else {
                __nv_bfloat16 h0 = __float2bfloat16(d0), h1 = __float2bfloat16(d1);
                __nv_bfloat16 h2 = __float2bfloat16(d2), h3 = __float2bfloat16(d3);
                __nv_bfloat162 hv0(h0, h1), hv1(h2, h3);
                __nv_bfloat162 lv0(__float2bfloat16(d0 - __bfloat162float(h0)),
                                   __float2bfloat16(d1 - __bfloat162float(h1)));
                __nv_bfloat162 lv1(__float2bfloat16(d2 - __bfloat162float(h2)),
                                   __float2bfloat16(d3 - __bfloat162float(h3)));
                *reinterpret_cast<__nv_bfloat162*>(Ch + (long long)r * ldc + c)       = hv0;
                *reinterpret_cast<__nv_bfloat162*>(Cl + (long long)r * ldc + c)       = lv0;
                *reinterpret_cast<__nv_bfloat162*>(Ch + (long long)(r + 8) * ldc + c) = hv1;
                *reinterpret_cast<__nv_bfloat162*>(Cl + (long long)(r + 8) * ldc + c) = lv1;
            }
        }
    }
}

// ---------------------------------------------------------------------------
// fp32 -> (hi, lo) bf16 split, elementwise
// ---------------------------------------------------------------------------
__global__ void __launch_bounds__(256)
convsplit(const float4* __restrict__ x, __nv_bfloat162* __restrict__ hi,
          __nv_bfloat162* __restrict__ lo, long long n4)
{
    long long i = (long long)blockIdx.x * 256 + threadIdx.x;
    if (i >= n4) return;
    float4 v = x[i];
    __nv_bfloat16 h0 = __float2bfloat16(v.x), h1 = __float2bfloat16(v.y);
    __nv_bfloat16 h2 = __float2bfloat16(v.z), h3 = __float2bfloat16(v.w);
    hi[2 * i]     = __nv_bfloat162(h0, h1);
    hi[2 * i + 1] = __nv_bfloat162(h2, h3);
    lo[2 * i]     = __nv_bfloat162(__float2bfloat16(v.x - __bfloat162float(h0)),
                                   __float2bfloat16(v.y - __bfloat162float(h1)));
    lo[2 * i + 1] = __nv_bfloat162(__float2bfloat16(v.z - __bfloat162float(h2)),
                                   __float2bfloat16(v.w - __bfloat162float(h3)));
}

// ---------------------------------------------------------------------------
// Transpose + split: in[R,C] fp32 (ldin) -> out[C,R] (hi, lo) bf16 (ldout)
// grid: (C/32, R/32), block (32,8)
// ---------------------------------------------------------------------------
__global__ void __launch_bounds__(256)
tsplit(const float* __restrict__ in, int ldin, __nv_bfloat16* __restrict__ oh,
       __nv_bfloat16* __restrict__ ol, int ldout)
{
    __shared__ float t[32][33];
    int bx = blockIdx.x * 32, by = blockIdx.y * 32;
    int tx = threadIdx.x, ty = threadIdx.y;
    #pragma unroll
    for (int j = ty; j < 32; j += 8)
        t[j][tx] = in[(long long)(by + j) * ldin + bx + tx];
    __syncthreads();
    #pragma unroll
    for (int j = ty; j < 32; j += 8) {
        float v = t[tx][j];
        __nv_bfloat16 h = __float2bfloat16(v);
        long long o = (long long)(bx + j) * ldout + by + tx;
        oh[o] = h;
        ol[o] = __float2bfloat16(v - __bfloat162float(h));
    }
}

// ---------------------------------------------------------------------------
// Neox-style RoPE in place on Q and K inside g_qkv
// ---------------------------------------------------------------------------
__global__ void __launch_bounds__(256)
rope_kernel(float* __restrict__ qkv, const int* __restrict__ positions)
{
    int idx = blockIdx.x * blockDim.x + threadIdx.x;
    int i = idx & 127;
    int h = (idx >> 7) % (NH + NKV);
    int t = idx / (128 * (NH + NKV));
    if (t >= T_SEQ) return;
    float pos = (float)positions[t];
    float inv = powf(10000.0f, -((2.0f * (float)i) / (float)HD));
    float f = pos * inv;
    float c = cosf(f), s = sinf(f);
    int col = (h < NH) ? (h * HD) : (K_OFF + (h - NH) * HD);
    float* p = qkv + (long long)t * QKV_COLS + col;
    float x1 = p[i], x2 = p[i + HD / 2];
    p[i]          = x1 * c - x2 * s;
    p[i + HD / 2] = x2 * c + x1 * s;
}

// ---------------------------------------------------------------------------
// Causal softmax over scores row q (reads only k <= q), writes split probs,
// zero-pads (q, tile boundary) which is exactly the range P.V reads.
// grid (T_SEQ, NH), 256 threads
// ---------------------------------------------------------------------------
__global__ void __launch_bounds__(256)
softmax2(const float* __restrict__ s, __nv_bfloat16* __restrict__ ph,
         __nv_bfloat16* __restrict__ pl)
{
    const int q = blockIdx.x;
    long long ro = ((long long)blockIdx.y * T_SEQ + q) * (long long)T_SEQ;
    const int len = q + 1;
    const int padEnd = ((q >> 7) + 1) << 7;
    const int tid = threadIdx.x, lane = tid & 31, wid = tid >> 5;
    __shared__ float red[8];

    float m = NEG_INF;
    for (int i = tid; i < len; i += 256) m = fmaxf(m, s[ro + i]);
    #pragma unroll
    for (int o = 16; o; o >>= 1) m = fmaxf(m, __shfl_xor_sync(0xffffffffu, m, o));
    if (lane == 0) red[wid] = m;
    __syncthreads();
    if (tid < 8) {
        float v = red[tid];
        #pragma unroll
        for (int o = 4; o; o >>= 1) v = fmaxf(v, __shfl_xor_sync(0xffu, v, o));
        if (tid == 0) red[0] = v;
    }
    __syncthreads();
    m = red[0];
    __syncthreads();

    float sum = 0.0f;
    for (int i = tid; i < len; i += 256) sum += expf(s[ro + i] - m);
    #pragma unroll
    for (int o = 16; o; o >>= 1) sum += __shfl_xor_sync(0xffffffffu, sum, o);
    if (lane == 0) red[wid] = sum;
    __syncthreads();
    if (tid < 8) {
        float v = red[tid];
        #pragma unroll
        for (int o = 4; o; o >>= 1) v += __shfl_xor_sync(0xffu, v, o);
        if (tid == 0) red[0] = v;
    }
    __syncthreads();
    float inv = 1.0f / red[0];

    for (int i = tid; i < len; i += 256) {
        float p = expf(s[ro + i] - m) * inv;
        __nv_bfloat16 h = __float2bfloat16(p);
        ph[ro + i] = h;
        pl[ro + i] = __float2bfloat16(p - __bfloat162float(h));
    }
    const __nv_bfloat16 zz = __float2bfloat16(0.0f);
    for (int i = len + tid; i < padEnd; i += 256) { ph[ro + i] = zz; pl[ro + i] = zz; }
}

// ---------------------------------------------------------------------------
// kernel_launch — graph-capturable, allocation-free
// ---------------------------------------------------------------------------
extern "C" void kernel_launch(void* const* d_in, const int* in_sizes, int n_in,
                              void* d_out, int out_size)
{
    const int*   positions = (const int*)  d_in[0];
    const float* hidden    = (const float*)d_in[1];
    const float* w_qkv     = (const float*)d_in[2];
    const float* w_o       = (const float*)d_in[3];
    float*       out       = (float*)d_out;

    float *qkv, *scores;
    __nv_bfloat16 *hch, *hcl, *wqh, *wql, *woh, *wol, *qch, *qcl, *vch, *vcl, *pph, *ppl, *ach, *acl;
    cudaGetSymbolAddress((void**)&qkv,    g_qkv);
    cudaGetSymbolAddress((void**)&scores, g_scores);
    cudaGetSymbolAddress((void**)&hch, g_hc_h);    cudaGetSymbolAddress((void**)&hcl, g_hc_l);
    cudaGetSymbolAddress((void**)&wqh, g_wqkvT_h); cudaGetSymbolAddress((void**)&wql, g_wqkvT_l);
    cudaGetSymbolAddress((void**)&woh, g_woT_h);   cudaGetSymbolAddress((void**)&wol, g_woT_l);
    cudaGetSymbolAddress((void**)&qch, g_qkvc_h);  cudaGetSymbolAddress((void**)&qcl, g_qkvc_l);
    cudaGetSymbolAddress((void**)&vch, g_vTc_h);   cudaGetSymbolAddress((void**)&vcl, g_vTc_l);
    cudaGetSymbolAddress((void**)&pph, g_p_h);     cudaGetSymbolAddress((void**)&ppl, g_p_l);
    cudaGetSymbolAddress((void**)&ach, g_attnc_h); cudaGetSymbolAddress((void**)&acl, g_attnc_l);

    cudaFuncSetAttribute(gemm_mma<0, 0>, cudaFuncAttributeMaxDynamicSharedMemorySize, GEMM_SMEM);
    cudaFuncSetAttribute(gemm_mma<1, 1>, cudaFuncAttributeMaxDynamicSharedMemorySize, GEMM_SMEM);
    cudaFuncSetAttribute(gemm_mma<2, 2>, cudaFuncAttributeMaxDynamicSharedMemorySize, GEMM_SMEM);

    // Operand prep: weight transposes + hidden split
    tsplit<<<dim3(QKV_COLS / 32, HID / 32), dim3(32, 8)>>>(w_qkv, QKV_COLS, wqh, wql, HID);
    tsplit<<<dim3(HID / 32, ATTN_COLS / 32), dim3(32, 8)>>>(w_o, HID, woh, wol, ATTN_COLS);
    {
        long long n4 = (long long)T_SEQ * HID / 4;
        convsplit<<<(unsigned)((n4 + 255) / 256), 256>>>((const float4*)hidden,
            (__nv_bfloat162*)hch, (__nv_bfloat162*)hcl, n4);
    }

    // 1) QKV projection -> fp32 qkv
    gemm_mma<0, 0><<<dim3(QKV_COLS / 128, T_SEQ / 128, 1), 256, GEMM_SMEM>>>(
        hch, hcl, wqh, wql, qkv, nullptr, nullptr,
        HID, HID, HID, QKV_COLS, 0, 0, 0, 1);

    // 2) RoPE on Q, K
    rope_kernel<<<(T_SEQ * (NH + NKV) * (HD / 2)) / 256, 256>>>(qkv, positions);

    // 3) split Q/K (full qkv for simplicity); transpose+split V -> vT
    {
        long long n4 = (long long)T_SEQ * QKV_COLS / 4;
        convsplit<<<(unsigned)((n4 + 255) / 256), 256>>>((const float4*)qkv,
            (__nv_bfloat162*)qch, (__nv_bfloat162*)qcl, n4);
    }
    tsplit<<<dim3((NKV * HD) / 32, T_SEQ / 32), dim3(32, 8)>>>(qkv + V_OFF, QKV_COLS, vch, vcl, T_SEQ);

    // 4) scores[h] = softcap(scale * Q_h K_{h/2}^T), upper tiles skipped
    gemm_mma<1, 1><<<dim3(T_SEQ / 128, T_SEQ / 128, NH), 256, GEMM_SMEM>>>(
        qch, qcl, qch + K_OFF, qcl + K_OFF, scores, nullptr, nullptr,
        HD, QKV_COLS, QKV_COLS, T_SEQ,
        (long long)HD, (long long)HD, (long long)T_SEQ * T_SEQ, 2);

    // 5) causal softmax -> split probs (zero-padded to tile boundary)
    softmax2<<<dim3(T_SEQ, NH), 256>>>(scores, pph, ppl);

    // 6) attn[h] = P_h @ V_{h/2}, K truncated at diagonal; direct split store
    gemm_mma<2, 2><<<dim3(HD / 128, T_SEQ / 128, NH), 256, GEMM_SMEM>>>(
        pph, ppl, vch, vcl, nullptr, ach, acl,
        T_SEQ, T_SEQ, T_SEQ, ATTN_COLS,
        (long long)T_SEQ * T_SEQ, (long long)HD * T_SEQ, (long long)HD, 2);

    // 7) output projection
    gemm_mma<0, 0><<<dim3(HID / 128, T_SEQ / 128, 1), 256, GEMM_SMEM>>>(
        ach, acl, woh, wol, out, nullptr, nullptr,
        ATTN_COLS, ATTN_COLS, ATTN_COLS, HID, 0, 0, 0, 1);
}